// round 5
// baseline (speedup 1.0000x reference)
#include <cuda_runtime.h>
#include <cstdint>

// ---------------------------------------------------------------------------
// MalConv fused, FFMA2 (packed f32x2) edition.
//
//   C[16000,256] = E[16000,4000] x W[4000,256]
//   Pairing: acc f32x2 = (g1_acc[j], g2_acc[j]);  mult = (W1[kk][j], W2[kk][j])
//            e broadcast stored pre-duplicated (e,e) in smem.
//   CTA: 16 patches x 128 col-pairs. Warp: 16 patches x 16 col-pairs.
//   Thread: 4 patches x 2 col-pairs -> 8 fma.rn.f32x2 per kk.
// ---------------------------------------------------------------------------

#define KERNEL_K    500
#define BATCH       8
#define SEQ_L       1000000
#define TM          16          // patches per CTA
#define TILES_PER_B 125         // 2000 / 16
#define KB          32          // K values per stage (4 k-pos * 8 ch)
#define KITERS      125         // 500 / 4

// dynamic smem layout (bytes)
#define SMEM_W      0           // b64 [2][32][128]  = 65536  (stage stride 32768)
#define SMEM_E      65536       // b64 [2][32][16]   = 8192   (stage stride 4096)
#define SMEM_EMB    73728       // f32 [257*8]       = 8224
#define SMEM_TOTAL  81952
#define ESTAGE      4096        // E stage stride in bytes  (FIXED: was 8192)

__device__ __align__(16) float2 g_Wpack[4000 * 128];  // [K][j] = (W1, W2)
__device__ int g_m[BATCH * 128];                      // max accum (float bits)

// ---------------------------------------------------------------------------
__global__ void pack_kernel(const float* __restrict__ W1,
                            const float* __restrict__ W2) {
    int i = blockIdx.x * 256 + threadIdx.x;
    if (i < BATCH * 128) g_m[i] = 0;
    if (i >= 4000 * 128) return;
    int j = i & 127;
    int K = i >> 7;
    int k = K >> 3;          // 0..499
    int c = K & 7;           // 0..7
    float2 v;
    v.x = W1[j * 4000 + c * KERNEL_K + k];
    v.y = W2[j * 4000 + c * KERNEL_K + k];
    g_Wpack[i] = v;
}

// ---------------------------------------------------------------------------
__device__ __forceinline__ void fma2(unsigned long long& d,
                                     unsigned long long a,
                                     unsigned long long b) {
    asm volatile("fma.rn.f32x2 %0, %1, %2, %0;" : "+l"(d) : "l"(a), "l"(b));
}
__device__ __forceinline__ unsigned long long dup2(float v) {
    unsigned int u = __float_as_uint(v);
    return ((unsigned long long)u << 32) | u;
}
__device__ __forceinline__ void st64(uint32_t a, unsigned long long v) {
    asm volatile("st.shared.b64 [%0], %1;" :: "r"(a), "l"(v) : "memory");
}
__device__ __forceinline__ void ld_v2b64(uint32_t a, unsigned long long& r0,
                                         unsigned long long& r1) {
    asm volatile("ld.shared.v2.b64 {%0, %1}, [%2];"
                 : "=l"(r0), "=l"(r1) : "r"(a));
}
__device__ __forceinline__ void cp_async16(uint32_t dst, const void* src) {
    asm volatile("cp.async.cg.shared.global [%0], [%1], 16;"
                 :: "r"(dst), "l"(src));
}
__device__ __forceinline__ void cp_commit() {
    asm volatile("cp.async.commit_group;");
}
template <int N>
__device__ __forceinline__ void cp_wait() {
    asm volatile("cp.async.wait_group %0;" :: "n"(N));
}

// ---------------------------------------------------------------------------
__global__ void __launch_bounds__(256, 2)
malconv_kernel(const int* __restrict__ x, const float* __restrict__ emb,
               const float* __restrict__ b1, const float* __restrict__ b2) {
    extern __shared__ __align__(16) char smem[];
    const uint32_t sbase = (uint32_t)__cvta_generic_to_shared(smem);
    const uint32_t sW = sbase + SMEM_W;
    const uint32_t sE = sbase + SMEM_E;
    float* sEmb = (float*)(smem + SMEM_EMB);

    const int tid    = threadIdx.x;
    const int lane   = tid & 31;
    const int w      = tid >> 5;          // 8 warps -> 16 col-pairs each
    const int lane_c = lane & 7;          // 8 col-groups of 2 col-pairs
    const int lane_p = lane >> 3;         // 4 patch-groups of 4 patches
    const int t      = blockIdx.x;
    const int b      = t / TILES_PER_B;
    const int tb     = t - b * TILES_PER_B;

    for (int i = tid; i < 257 * 8; i += 256) sEmb[i] = emb[i];

    // W stage copy: 32 KB per stage, 8 x 16B per thread, coalesced
    const char* wg = (const char*)g_Wpack;

    // E builder: 64 threads, one (patch, k-pos) each
    const bool builder = (tid < TM * 4);
    const int  bp  = tid >> 2;            // 0..15
    const int  bkp = tid & 3;             // 0..3
    const int* xp  = x + (size_t)b * SEQ_L
                       + ((size_t)tb * TM + bp) * KERNEL_K + bkp;

    unsigned long long acc[4][2];
#pragma unroll
    for (int i = 0; i < 4; i++) { acc[i][0] = 0ull; acc[i][1] = 0ull; }

    __syncthreads();                      // sEmb ready

    // ---- prologue: stage 0 ----
    {
        uint32_t d = sW + tid * 16;
        const char* g = wg + tid * 16;
#pragma unroll
        for (int q = 0; q < 8; q++) cp_async16(d + q * 4096, g + q * 4096);
        cp_commit();
    }
    int vx = builder ? xp[0] : 0;
    if (builder) {                        // build E stage 0
        const float4* er = (const float4*)(sEmb + (vx << 3));
        float4 e0 = er[0], e1 = er[1];
        uint32_t a = sE + (bkp * 8) * 128 + bp * 8;
        st64(a + 0 * 128, dup2(e0.x)); st64(a + 1 * 128, dup2(e0.y));
        st64(a + 2 * 128, dup2(e0.z)); st64(a + 3 * 128, dup2(e0.w));
        st64(a + 4 * 128, dup2(e1.x)); st64(a + 5 * 128, dup2(e1.y));
        st64(a + 6 * 128, dup2(e1.z)); st64(a + 7 * 128, dup2(e1.w));
        vx = xp[4];                       // prefetch iter 1
    }

    const uint32_t wbase0 = sW + (w * 16 + lane_c * 2) * 8;  // + s*32768 + kk*1024
    const uint32_t ebase0 = sE + lane_p * 32;                // + s*ESTAGE + kk*128

    for (int it = 0; it < KITERS; ++it) {
        const int s = it & 1;
        if (it + 1 < KITERS) {
            // stage W(it+1)
            uint32_t d = sW + (1 - s) * 32768 + tid * 16;
            const char* g = wg + (size_t)(it + 1) * 32768 + tid * 16;
#pragma unroll
            for (int q = 0; q < 8; q++) cp_async16(d + q * 4096, g + q * 4096);
            cp_commit();
            // build E(it+1) from prefetched vx
            if (builder) {
                const float4* er = (const float4*)(sEmb + (vx << 3));
                float4 e0 = er[0], e1 = er[1];
                uint32_t a = sE + (1 - s) * ESTAGE + (bkp * 8) * 128 + bp * 8;
                st64(a + 0 * 128, dup2(e0.x)); st64(a + 1 * 128, dup2(e0.y));
                st64(a + 2 * 128, dup2(e0.z)); st64(a + 3 * 128, dup2(e0.w));
                st64(a + 4 * 128, dup2(e1.x)); st64(a + 5 * 128, dup2(e1.y));
                st64(a + 6 * 128, dup2(e1.z)); st64(a + 7 * 128, dup2(e1.w));
                if (it + 2 < KITERS) vx = xp[(it + 2) * 4];  // latency hidden
            }
            cp_wait<1>();
        } else {
            cp_wait<0>();
        }
        __syncthreads();                  // stage(it) data visible

        // ---- FFMA2 mainloop: 32 kk x 8 fma2 ----
        const uint32_t wb = wbase0 + s * 32768;
        const uint32_t eb = ebase0 + s * ESTAGE;
#pragma unroll
        for (int kk = 0; kk < KB; kk++) {
            unsigned long long e0, e1, e2, e3, w0, w1;
            ld_v2b64(eb + kk * 128,      e0, e1);
            ld_v2b64(eb + kk * 128 + 16, e2, e3);
            ld_v2b64(wb + kk * 1024,     w0, w1);
            fma2(acc[0][0], e0, w0); fma2(acc[0][1], e0, w1);
            fma2(acc[1][0], e1, w0); fma2(acc[1][1], e1, w1);
            fma2(acc[2][0], e2, w0); fma2(acc[2][1], e2, w1);
            fma2(acc[3][0], e3, w0); fma2(acc[3][1], e3, w1);
        }
        __syncthreads();                  // compute(it) done; buffers reusable
    }

    // ---- epilogue: bias + GLU + relu + max over patches + warp reduce ----
    const int j0 = w * 16 + lane_c * 2;
    float hm[2] = {0.f, 0.f};
#pragma unroll
    for (int c = 0; c < 2; c++) {
        float bb1 = b1[j0 + c];
        float bb2 = b2[j0 + c];
#pragma unroll
        for (int i = 0; i < 4; i++) {
            unsigned long long a = acc[i][c];
            float g1 = __uint_as_float((unsigned)(a & 0xffffffffull)) + bb1;
            float g2 = __uint_as_float((unsigned)(a >> 32)) + bb2;
            float sg = 1.f / (1.f + expf(-g2));
            float h  = fmaxf(g1 * sg, 0.f);
            hm[c] = fmaxf(hm[c], h);
        }
        // reduce over the 4 lane_p groups (lanes differ by 8 and 16)
        hm[c] = fmaxf(hm[c], __shfl_xor_sync(0xFFFFFFFFu, hm[c], 8));
        hm[c] = fmaxf(hm[c], __shfl_xor_sync(0xFFFFFFFFu, hm[c], 16));
        if (lane_p == 0)
            atomicMax(&g_m[b * 128 + j0 + c], __float_as_int(hm[c]));
    }
}

// ---------------------------------------------------------------------------
__global__ void fc_kernel(const float* __restrict__ fcW,
                          const float* __restrict__ fcb,
                          float* __restrict__ out) {
    int w    = threadIdx.x >> 5;
    int lane = threadIdx.x & 31;
    for (int pair = w; pair < BATCH * 2; pair += 8) {
        int b = pair >> 1;
        int j = pair & 1;
        float s = 0.f;
        for (int o = lane; o < 128; o += 32)
            s += __int_as_float(g_m[b * 128 + o]) * fcW[j * 128 + o];
#pragma unroll
        for (int off = 16; off; off >>= 1)
            s += __shfl_down_sync(0xFFFFFFFFu, s, off);
        if (lane == 0) out[b * 2 + j] = s + fcb[j];
    }
}

// ---------------------------------------------------------------------------
extern "C" void kernel_launch(void* const* d_in, const int* in_sizes, int n_in,
                              void* d_out, int out_size) {
    const int*   x   = (const int*)d_in[0];
    const float* emb = (const float*)d_in[1];
    const float* W1  = (const float*)d_in[2];
    const float* b1  = (const float*)d_in[3];
    const float* W2  = (const float*)d_in[4];
    const float* b2  = (const float*)d_in[5];
    const float* fcW = (const float*)d_in[6];
    const float* fcb = (const float*)d_in[7];
    float*       out = (float*)d_out;

    cudaFuncSetAttribute(malconv_kernel,
                         cudaFuncAttributeMaxDynamicSharedMemorySize,
                         SMEM_TOTAL);

    pack_kernel<<<(4000 * 128 + 255) / 256, 256>>>(W1, W2);
    malconv_kernel<<<TILES_PER_B * BATCH, 256, SMEM_TOTAL>>>(x, emb, b1, b2);
    fc_kernel<<<1, 256>>>(fcW, fcb, out);
}

// round 7
// speedup vs baseline: 3.2311x; 3.2311x over previous
#include <cuda_runtime.h>
#include <cuda_bf16.h>
#include <cstdint>

// ---------------------------------------------------------------------------
// MalConv via mma.sync (HMMA) bf16x3 split GEMM.  (tcgen05 unavailable:
// harness compiles via compute_103 virtual arch, which rejects 'a' features.)
//
//   C[16000,256] = E[16000,4000] x W[4000,256]
//   fp32 emulated: Ahi*Bhi + Ahi*Blo + Alo*Bhi (bf16 operands, fp32 accum).
//   Columns interleaved (g1_j, g2_j) so mma C-fragment pairs = (g1, g2).
//   CTA: 128 patches x 128 cols, 8 warps (4m x 2n), warp tile 32x64.
//   K: 125 chunks of 32 (4000 exact). Grid: 125 m-tiles x 2 n-tiles = 250.
// ---------------------------------------------------------------------------

#define CHUNKS   125
#define BATCH    8

// stage layout (bytes): Ahi 8K | Alo 8K | Bhi 8K | Blo 8K  = 32 KB
#define AH_OFF   0
#define AL_OFF   8192
#define BH_OFF   16384
#define BL_OFF   24576
#define STG      32768
// after 2 stages:
#define EMBH_OFF 65536          // uint4[257] bf16x8 rows
#define EMBL_OFF 69648
#define SMEM_TOTAL 73760

__device__ __align__(16) unsigned char g_B[CHUNKS * 32768]; // [c][hl][256n][64B]
__device__ int g_m[BATCH * 128];

// ---------------------------------------------------------------------------
__global__ void pack_kernel(const float* __restrict__ W1,
                            const float* __restrict__ W2) {
    int i = blockIdx.x * 256 + threadIdx.x;
    if (i < BATCH * 128) g_m[i] = 0;
    if (i >= CHUNKS * 2 * 256 * 32) return;
    int kk = i & 31;                 // k within chunk
    int n  = (i >> 5) & 255;         // interleaved col: j = n>>1, t = n&1
    int hl = (i >> 13) & 1;          // 0 = hi, 1 = lo
    int c  = i >> 14;                // chunk
    int K  = c * 32 + kk;            // 0..3999
    int k  = K >> 3, ch = K & 7;
    int j  = n >> 1;
    float v = (n & 1) ? W2[j * 4000 + ch * 500 + k]
                      : W1[j * 4000 + ch * 500 + k];
    __nv_bfloat16 hi = __float2bfloat16(v);
    float out = hl ? (v - __bfloat162float(hi)) : v;
    int quad = kk >> 3;
    size_t addr = (size_t)c * 32768 + hl * 16384 + n * 64
                + (((quad ^ (n & 3)) << 4) + (kk & 7) * 2);
    *(__nv_bfloat16*)(g_B + addr) = __float2bfloat16(out);
}

// ---------------------------------------------------------------------------
__device__ __forceinline__ void cp_async16(uint32_t dst, const void* src) {
    asm volatile("cp.async.cg.shared.global [%0], [%1], 16;" :: "r"(dst), "l"(src));
}
__device__ __forceinline__ void cp_commit() { asm volatile("cp.async.commit_group;"); }
template <int N> __device__ __forceinline__ void cp_wait() {
    asm volatile("cp.async.wait_group %0;" :: "n"(N));
}
__device__ __forceinline__ void ldsm4(uint32_t a, uint32_t* r) {
    asm volatile("ldmatrix.sync.aligned.m8n8.x4.shared.b16 {%0,%1,%2,%3}, [%4];"
                 : "=r"(r[0]), "=r"(r[1]), "=r"(r[2]), "=r"(r[3]) : "r"(a));
}
__device__ __forceinline__ void mma16816(float* d, const uint32_t* a,
                                         uint32_t b0, uint32_t b1) {
    asm volatile(
        "mma.sync.aligned.m16n8k16.row.col.f32.bf16.bf16.f32 "
        "{%0,%1,%2,%3}, {%4,%5,%6,%7}, {%8,%9}, {%0,%1,%2,%3};"
        : "+f"(d[0]), "+f"(d[1]), "+f"(d[2]), "+f"(d[3])
        : "r"(a[0]), "r"(a[1]), "r"(a[2]), "r"(a[3]), "r"(b0), "r"(b1));
}
__device__ __forceinline__ uint32_t swz(int row, int quad) {
    return row * 64 + ((quad ^ (row & 3)) << 4);
}

// ---------------------------------------------------------------------------
__global__ void __launch_bounds__(256, 2)
malconv_kernel(const int* __restrict__ x, const float* __restrict__ emb,
               const float* __restrict__ b1, const float* __restrict__ b2) {
    extern __shared__ __align__(16) char smem[];
    const uint32_t sb = (uint32_t)__cvta_generic_to_shared(smem);
    const int tid  = threadIdx.x;
    const int lane = tid & 31;
    const int wid  = tid >> 5;
    const int wm   = wid >> 1;          // 0..3  (m-warp)
    const int wn   = wid & 1;           // 0..1  (n-warp)
    const int mt   = blockIdx.x >> 1;   // 0..124
    const int nt   = blockIdx.x & 1;    // 0..1

    // bf16 hi/lo embedding tables (16B per row)
    uint4* eH = (uint4*)(smem + EMBH_OFF);
    uint4* eL = (uint4*)(smem + EMBL_OFF);
    for (int i = tid; i < 257 * 8; i += 256) {
        float v = emb[i];
        __nv_bfloat16 hi = __float2bfloat16(v);
        __nv_bfloat16 lo = __float2bfloat16(v - __bfloat162float(hi));
        ((__nv_bfloat16*)eH)[i] = hi;
        ((__nv_bfloat16*)eL)[i] = lo;
    }

    float acc[2][8][4];
#pragma unroll
    for (int a = 0; a < 2; a++)
#pragma unroll
        for (int b = 0; b < 8; b++)
#pragma unroll
            for (int q = 0; q < 4; q++) acc[a][b][q] = 0.f;

    // builder: thread -> (patch p = tid>>1, kp pair base = (tid&1)*2)
    const int bp  = tid >> 1;
    const int bk2 = (tid & 1) * 2;
    const int* xp = x + (size_t)(mt * 128 + bp) * 500 + bk2;

    auto build_A = [&](int buf, int2 xv) {
        char* A = smem + buf * STG;
#pragma unroll
        for (int q = 0; q < 2; q++) {
            int v  = q ? xv.y : xv.x;
            int kp = bk2 + q;
            uint32_t off = swz(bp, kp);
            *(uint4*)(A + AH_OFF + off) = eH[v];
            *(uint4*)(A + AL_OFF + off) = eL[v];
        }
    };
    auto load_B = [&](int c, int buf) {
        uint32_t d = sb + buf * STG;
        const unsigned char* g = g_B + (size_t)c * 32768 + nt * 8192;
        cp_async16(d + BH_OFF + tid * 16,        g + tid * 16);
        cp_async16(d + BH_OFF + 4096 + tid * 16, g + 4096 + tid * 16);
        cp_async16(d + BL_OFF + tid * 16,        g + 16384 + tid * 16);
        cp_async16(d + BL_OFF + 4096 + tid * 16, g + 16384 + 4096 + tid * 16);
        cp_commit();
    };

    // ldmatrix lane-relative offsets (within a stage)
    uint32_t a_rel[2][2], b_rel[2][4];
#pragma unroll
    for (int ks = 0; ks < 2; ks++) {
#pragma unroll
        for (int fm = 0; fm < 2; fm++) {
            int row  = wm * 32 + fm * 16 + (lane & 15);
            int quad = 2 * ks + (lane >> 4);
            a_rel[ks][fm] = AH_OFF + swz(row, quad);
        }
#pragma unroll
        for (int f2 = 0; f2 < 4; f2++) {
            int mat  = lane >> 3;
            int row  = wn * 64 + f2 * 16 + (mat >> 1) * 8 + (lane & 7);
            int quad = 2 * ks + (mat & 1);
            b_rel[ks][f2] = BH_OFF + swz(row, quad);
        }
    }

    __syncthreads();            // emb tables ready (also before first build)

    // prologue: chunk 0
    load_B(0, 0);
    build_A(0, *(const int2*)xp);
    int2 xv = *(const int2*)(xp + 4);      // prefetch chunk 1

    for (int it = 0; it < CHUNKS; ++it) {
        const int s = it & 1;
        __syncthreads();        // stage s^1 free (prev compute done)
        if (it + 1 < CHUNKS) {
            load_B(it + 1, 1 - s);
            build_A(1 - s, xv);
            if (it + 2 < CHUNKS) xv = *(const int2*)(xp + (it + 2) * 4);
            cp_wait<1>();       // B(it) arrived
        } else {
            cp_wait<0>();
        }
        __syncthreads();        // stage s (cp.async + STS) visible to all

        const uint32_t stg = sb + s * STG;
#pragma unroll
        for (int ks = 0; ks < 2; ks++) {
            uint32_t ah[2][4], al[2][4];
            ldsm4(stg + a_rel[ks][0], ah[0]);
            ldsm4(stg + a_rel[ks][1], ah[1]);
            ldsm4(stg + a_rel[ks][0] + 8192, al[0]);
            ldsm4(stg + a_rel[ks][1] + 8192, al[1]);
#pragma unroll
            for (int f2 = 0; f2 < 4; f2++) {
                uint32_t bh[4], bl[4];
                ldsm4(stg + b_rel[ks][f2], bh);
                ldsm4(stg + b_rel[ks][f2] + 8192, bl);
#pragma unroll
                for (int fm = 0; fm < 2; fm++) {
#pragma unroll
                    for (int fb = 0; fb < 2; fb++) {
                        float* d = acc[fm][f2 * 2 + fb];
                        mma16816(d, ah[fm], bh[2 * fb], bh[2 * fb + 1]);
                        mma16816(d, ah[fm], bl[2 * fb], bl[2 * fb + 1]);
                        mma16816(d, al[fm], bh[2 * fb], bh[2 * fb + 1]);
                    }
                }
            }
        }
    }

    // ---- epilogue: bias + GLU + relu + max over patches ----
    const int wbase = mt * 128 + wm * 32;
    const bool straddle = (wbase / 2000) != ((wbase + 31) / 2000);
#pragma unroll
    for (int fn = 0; fn < 8; fn++) {
        int j = nt * 64 + wn * 32 + fn * 4 + (lane & 3);
        float bb1 = b1[j], bb2 = b2[j];
        float h[2][2];
#pragma unroll
        for (int fm = 0; fm < 2; fm++) {
#pragma unroll
            for (int hf = 0; hf < 2; hf++) {
                float g1 = acc[fm][fn][hf * 2 + 0] + bb1;
                float g2 = acc[fm][fn][hf * 2 + 1] + bb2;
                h[fm][hf] = fmaxf(g1 * (1.f / (1.f + expf(-g2))), 0.f);
            }
        }
        if (!straddle) {
            float hm = fmaxf(fmaxf(h[0][0], h[0][1]), fmaxf(h[1][0], h[1][1]));
            hm = fmaxf(hm, __shfl_xor_sync(0xFFFFFFFFu, hm, 4));
            hm = fmaxf(hm, __shfl_xor_sync(0xFFFFFFFFu, hm, 8));
            hm = fmaxf(hm, __shfl_xor_sync(0xFFFFFFFFu, hm, 16));
            if ((lane >> 2) == 0)
                atomicMax(&g_m[(wbase / 2000) * 128 + j], __float_as_int(hm));
        } else {
#pragma unroll
            for (int fm = 0; fm < 2; fm++) {
#pragma unroll
                for (int hf = 0; hf < 2; hf++) {
                    int gp = wbase + fm * 16 + (lane >> 2) + hf * 8;
                    atomicMax(&g_m[(gp / 2000) * 128 + j],
                              __float_as_int(h[fm][hf]));
                }
            }
        }
    }
}

// ---------------------------------------------------------------------------
__global__ void fc_kernel(const float* __restrict__ fcW,
                          const float* __restrict__ fcb,
                          float* __restrict__ out) {
    int w    = threadIdx.x >> 5;
    int lane = threadIdx.x & 31;
    for (int pair = w; pair < BATCH * 2; pair += 8) {
        int b = pair >> 1;
        int j = pair & 1;
        float s = 0.f;
        for (int o = lane; o < 128; o += 32)
            s += __int_as_float(g_m[b * 128 + o]) * fcW[j * 128 + o];
#pragma unroll
        for (int off = 16; off; off >>= 1)
            s += __shfl_down_sync(0xFFFFFFFFu, s, off);
        if (lane == 0) out[b * 2 + j] = s + fcb[j];
    }
}

// ---------------------------------------------------------------------------
extern "C" void kernel_launch(void* const* d_in, const int* in_sizes, int n_in,
                              void* d_out, int out_size) {
    const int*   x   = (const int*)d_in[0];
    const float* emb = (const float*)d_in[1];
    const float* W1  = (const float*)d_in[2];
    const float* b1  = (const float*)d_in[3];
    const float* W2  = (const float*)d_in[4];
    const float* b2  = (const float*)d_in[5];
    const float* fcW = (const float*)d_in[6];
    const float* fcb = (const float*)d_in[7];
    float*       out = (float*)d_out;

    cudaFuncSetAttribute(malconv_kernel,
                         cudaFuncAttributeMaxDynamicSharedMemorySize, SMEM_TOTAL);

    pack_kernel<<<(CHUNKS * 2 * 256 * 32 + 255) / 256, 256>>>(W1, W2);
    malconv_kernel<<<250, 256, SMEM_TOTAL>>>(x, emb, b1, b2);
    fc_kernel<<<1, 256>>>(fcW, fcb, out);
}